// round 14
// baseline (speedup 1.0000x reference)
#include <cuda_runtime.h>

constexpr int C_ = 64, K_ = 48, MQ_MAX = 25000;
constexpr int NSLOT = 5, QPS = 2, THREADS1 = NSLOT * 64;   // 320
constexpr int KSTR = 68, CTXSTR = 68;
constexpr int KINQ = K_ * KSTR;                            // 3264 floats per query

// kernel1 smem offsets (floats)
constexpr int O_WQT=0, O_WK=4096, O_WVT=8192, O_BQ=12288, O_BV=12352,
  O_QPW=12416, O_QPB=12608, O_KPW=12672, O_KPB=12864, O_SLOT=12928;
// per-slot offsets (floats); [q] sub-indexed inside
constexpr int S_KIN=0;                // 2*3264 = 6528
constexpr int S_U=6528;               // 2*256
constexpr int S_QV=7040;              // 2*64
constexpr int S_QIN=7168;             // 2*64
constexpr int S_SB=7296;              // 2*192
constexpr int S_CTX=7680;             // 2*272
constexpr int S_REL4=8224;            // 2*192 (float4[48] per q)
constexpr int S_MSK=8608;             // 2*48
constexpr int S_KIX=8704;             // 2*48 ints
constexpr int S_INV=8800;             // 2*4
constexpr int SLOT_FL=8816;
constexpr int SMEM1_BYTES = (O_SLOT + NSLOT*SLOT_FL) * 4;  // 228032

// kernel2 smem offsets (floats) — 4 groups x 128 threads, Q8 (unchanged)
constexpr int Q_WOT=0, Q_W1T=4096, Q_W2T=20480, Q_WOUT=36864, Q_BO=40960,
  Q_B1=41024, Q_B2=41280, Q_BN1S=41344, Q_BN1T=41408, Q_BN2S=41472,
  Q_BN2T=41536, Q_OUTB=41600, Q_GRP=41664, GRP_FL=3072;
constexpr int SMEM2_BYTES = (Q_GRP + 4*GRP_FL) * 4;        // 215808

__device__ float g_obuf[MQ_MAX * C_];

#define BAR64(id)  asm volatile("bar.sync %0, 64;"  :: "r"(id) : "memory")
#define BAR128(id) asm volatile("bar.sync %0, 128;" :: "r"(id) : "memory")

// Block-local detection of key_mask storage: 0=uint8, 1=int32, 2=float32.
__device__ __forceinline__ int detect_mask_mode(const unsigned char* __restrict__ b,
                                                int* scratch, int tid, int nthr) {
    unsigned my123 = 0, my3f = 0;
    for (int i = tid * 16; i < tid * 16 + 16; i++) {
        if (i < 4096) {
            unsigned v = b[i];
            if ((i & 3) && v) my123 = 1;
            if ((i & 3) == 3 && v == 0x3fu) my3f = 1;
        }
    }
    unsigned w123 = __ballot_sync(0xffffffffu, my123 != 0);
    unsigned w3f  = __ballot_sync(0xffffffffu, my3f  != 0);
    int nw = nthr >> 5;
    if ((tid & 31) == 0) {
        scratch[(tid >> 5) * 2 + 0] = (w123 != 0);
        scratch[(tid >> 5) * 2 + 1] = (w3f  != 0);
    }
    __syncthreads();
    if (tid == 0) {
        int a123 = 0, a3f = 0;
        for (int w = 0; w < nw; w++) { a123 |= scratch[w*2]; a3f |= scratch[w*2+1]; }
        scratch[64] = (a123 == 0) ? 1 : (a3f ? 2 : 0);
    }
    __syncthreads();
    int mode = scratch[64];
    __syncthreads();
    return mode;
}

// ============================================================================
// attn: gather + pos-proj + restructured MHA -> g_obuf (+ d_out tail zero)
// 5 slots x 64 lanes, 2 queries per slot: weight LDS amortized over 2 queries.
// ============================================================================
__global__ __launch_bounds__(THREADS1, 1) void attn_kernel(
    const float* __restrict__ vf, const float* __restrict__ vcoord,
    const float* __restrict__ qcoord, const int* __restrict__ kidx,
    const void* __restrict__ kmask,
    const float* __restrict__ qpw_g, const float* __restrict__ qpb_g,
    const float* __restrict__ kpw_g, const float* __restrict__ kpb_g,
    const float* __restrict__ ipW, const float* __restrict__ ipB, int m,
    float* __restrict__ out, long long out_size)
{
    extern __shared__ float sm[];
    const int tid = threadIdx.x;

    // zero d_out tail beyond m*64 (poison insurance; attn precedes ffn in-stream)
    for (long long i = (long long)m * 64 + (long long)blockIdx.x * blockDim.x + tid;
         i < out_size; i += (long long)gridDim.x * blockDim.x)
        out[i] = 0.f;

    for (int i = tid; i < 4096; i += THREADS1) {
        int c = i & 63, cp = i >> 6;
        sm[O_WQT + i] = ipW[c * 64 + cp];           // wq^T
        sm[O_WK  + i] = ipW[4096 + i];              // wk row-major
        sm[O_WVT + i] = ipW[(128 + c) * 64 + cp];   // wv^T
    }
    if (tid < 64) {
        sm[O_BQ + tid] = ipB[tid];
        sm[O_BV + tid] = ipB[128 + tid];
        sm[O_QPB + tid] = qpb_g[tid];
        sm[O_KPB + tid] = kpb_g[tid];
    }
    if (tid < 192) { sm[O_QPW + tid] = qpw_g[tid]; sm[O_KPW + tid] = kpw_g[tid]; }
    __syncthreads();

    const int mode = detect_mask_mode((const unsigned char*)kmask,
                                      (int*)(sm + O_SLOT), tid, THREADS1);

    const int slot = tid >> 6, lane = tid & 63;
    const int bid = slot + 1;
    float* S = sm + O_SLOT + slot * SLOT_FL;
    float* kin = S + S_KIN;   float* u_s = S + S_U;   float* qv_s = S + S_QV;
    float* qin_s = S + S_QIN; float* sb = S + S_SB;   float* ctx = S + S_CTX;
    float4* rel4 = (float4*)(S + S_REL4);             // [q*48 + k]
    float* msk = S + S_MSK;   int* kix = (int*)(S + S_KIX);
    float* inv = S + S_INV;

    const float kw0 = sm[O_KPW + lane*3+0], kw1 = sm[O_KPW + lane*3+1],
                kw2 = sm[O_KPW + lane*3+2], kb_ = sm[O_KPB + lane];

    const int step = gridDim.x * NSLOT * QPS;

    // prefetch state for both queries of this slot
    float nc0[2], nc1[2], nc2[2], nmv[2] = {0.f,0.f};
    float nvx[2] = {0.f,0.f}, nvy[2] = {0.f,0.f}, nvz[2] = {0.f,0.f};
    int nvi[2] = {0,0};
    {
        int qb = blockIdx.x * NSLOT * QPS + slot * QPS;
        #pragma unroll
        for (int qq = 0; qq < QPS; qq++) {
            int qn = qb + qq;
            int qc_ = (qn < m) ? qn : 0;
            nc0[qq] = __ldg(&qcoord[qc_*3+0]);
            nc1[qq] = __ldg(&qcoord[qc_*3+1]);
            nc2[qq] = __ldg(&qcoord[qc_*3+2]);
            if (lane < K_) {
                const int idx = qc_ * K_ + lane;
                nvi[qq] = __ldg(&kidx[idx]);
                if (mode == 0)      nmv[qq] = ((const unsigned char*)kmask)[idx] ? 1.f : 0.f;
                else if (mode == 1) nmv[qq] = ((const int*)kmask)[idx] ? 1.f : 0.f;
                else                nmv[qq] = (((const float*)kmask)[idx] != 0.f) ? 1.f : 0.f;
                nvx[qq] = __ldg(&vcoord[nvi[qq]*3+0]);
                nvy[qq] = __ldg(&vcoord[nvi[qq]*3+1]);
                nvz[qq] = __ldg(&vcoord[nvi[qq]*3+2]);
            }
        }
    }

    for (int q0 = blockIdx.x * NSLOT * QPS; q0 < m; q0 += step) {
        const int qb = q0 + slot * QPS;          // first of this slot's 2 queries
        bool v[2] = { qb < m, qb + 1 < m };

        // P01: consume prefetched data for both queries
        #pragma unroll
        for (int qq = 0; qq < QPS; qq++) {
            if (v[qq]) {
                const float c0 = nc0[qq], c1 = nc1[qq], c2 = nc2[qq];
                if (lane < K_) {
                    msk[qq*48 + lane] = nmv[qq];
                    kix[qq*48 + lane] = nvi[qq];
                    float4 r;
                    r.x = nvx[qq] - c0; r.y = nvy[qq] - c1; r.z = nvz[qq] - c2; r.w = 0.f;
                    rel4[qq*48 + lane] = r;
                }
                float t = sm[O_QPB + lane];
                t = fmaf(sm[O_QPW + lane*3+0], c0, t);
                t = fmaf(sm[O_QPW + lane*3+1], c1, t);
                t = fmaf(sm[O_QPW + lane*3+2], c2, t);
                qin_s[qq*64 + lane] = fmaxf(t, 0.f);
            }
        }
        // prefetch next iteration's queries
        #pragma unroll
        for (int qq = 0; qq < QPS; qq++) {
            int qn = qb + qq + step;
            int qc_ = (qn < m) ? qn : 0;
            nc0[qq] = __ldg(&qcoord[qc_*3+0]);
            nc1[qq] = __ldg(&qcoord[qc_*3+1]);
            nc2[qq] = __ldg(&qcoord[qc_*3+2]);
            if (lane < K_) {
                const int idx = qc_ * K_ + lane;
                nvi[qq] = __ldg(&kidx[idx]);
                if (mode == 0)      nmv[qq] = ((const unsigned char*)kmask)[idx] ? 1.f : 0.f;
                else if (mode == 1) nmv[qq] = ((const int*)kmask)[idx] ? 1.f : 0.f;
                else                nmv[qq] = (((const float*)kmask)[idx] != 0.f) ? 1.f : 0.f;
                nvx[qq] = __ldg(&vcoord[nvi[qq]*3+0]);
                nvy[qq] = __ldg(&vcoord[nvi[qq]*3+1]);
                nvz[qq] = __ldg(&vcoord[nvi[qq]*3+2]);
            }
        }
        BAR64(bid);

        // P2: qv = (qin @ wq^T + bq) * 0.25 — weight read shared by 2 queries
        {
            float a0 = sm[O_BQ + lane], a1 = a0;
            #pragma unroll
            for (int cp = 0; cp < 64; cp += 4) {
                float4 x0 = *(const float4*)&qin_s[cp];
                float4 x1 = *(const float4*)&qin_s[64 + cp];
                float w0 = sm[O_WQT + (cp+0)*64 + lane];
                float w1 = sm[O_WQT + (cp+1)*64 + lane];
                float w2 = sm[O_WQT + (cp+2)*64 + lane];
                float w3 = sm[O_WQT + (cp+3)*64 + lane];
                a0 = fmaf(x0.x,w0, fmaf(x0.y,w1, fmaf(x0.z,w2, fmaf(x0.w,w3, a0))));
                a1 = fmaf(x1.x,w0, fmaf(x1.y,w1, fmaf(x1.z,w2, fmaf(x1.w,w3, a1))));
            }
            qv_s[lane]      = a0 * 0.25f;
            qv_s[64 + lane] = a1 * 0.25f;
        }
        BAR64(bid);

        // P3: u[h] = wk_h^T @ q_h (weights shared) ; gather k_in for both queries
        {
            #pragma unroll
            for (int h = 0; h < 4; h++) {
                float a0 = 0.f, a1 = 0.f;
                #pragma unroll
                for (int j4 = 0; j4 < 4; j4++) {
                    float4 qv0 = *(const float4*)&qv_s[h*16 + j4*4];
                    float4 qv1 = *(const float4*)&qv_s[64 + h*16 + j4*4];
                    float w0 = sm[O_WK + (h*16+j4*4+0)*64 + lane];
                    float w1 = sm[O_WK + (h*16+j4*4+1)*64 + lane];
                    float w2 = sm[O_WK + (h*16+j4*4+2)*64 + lane];
                    float w3 = sm[O_WK + (h*16+j4*4+3)*64 + lane];
                    a0 = fmaf(qv0.x,w0, fmaf(qv0.y,w1, fmaf(qv0.z,w2, fmaf(qv0.w,w3, a0))));
                    a1 = fmaf(qv1.x,w0, fmaf(qv1.y,w1, fmaf(qv1.z,w2, fmaf(qv1.w,w3, a1))));
                }
                u_s[h*64 + lane]       = a0;
                u_s[256 + h*64 + lane] = a1;
            }
            #pragma unroll
            for (int qq = 0; qq < QPS; qq++) {
                if (!v[qq]) continue;
                const int* kxq = kix + qq*48;
                float* kinq = kin + qq*KINQ;
                #pragma unroll
                for (int kb = 0; kb < K_; kb += 16) {
                    float fv[16];
                    #pragma unroll
                    for (int j = 0; j < 16; j++)
                        fv[j] = __ldg(&vf[kxq[kb+j] * 64 + lane]);
                    #pragma unroll
                    for (int j = 0; j < 16; j++) {
                        float4 r = rel4[qq*48 + kb + j];
                        float kp = kb_;
                        kp = fmaf(kw0, r.x, kp);
                        kp = fmaf(kw1, r.y, kp);
                        kp = fmaf(kw2, r.z, kp);
                        kinq[(kb+j)*KSTR + lane] = fv[j] + fmaxf(kp, 0.f);
                    }
                }
            }
        }
        BAR64(bid);

        // P4: scores — lane = key, all 4 heads, both queries (float4 kin reads)
        if (lane < K_) {
            const int k = lane;
            #pragma unroll
            for (int qq = 0; qq < QPS; qq++) {
                if (!v[qq]) continue;
                const float4* kr4 = (const float4*)&kin[qq*KINQ + k*KSTR];
                const float4* u4 = (const float4*)(u_s + qq*256);
                float4 acc = make_float4(0.f, 0.f, 0.f, 0.f);
                #pragma unroll 4
                for (int c4 = 0; c4 < 16; c4++) {
                    float4 kv = kr4[c4];
                    float4 a0 = u4[c4], a1 = u4[16+c4], a2 = u4[32+c4], a3 = u4[48+c4];
                    acc.x = fmaf(kv.x,a0.x, fmaf(kv.y,a0.y, fmaf(kv.z,a0.z, fmaf(kv.w,a0.w, acc.x))));
                    acc.y = fmaf(kv.x,a1.x, fmaf(kv.y,a1.y, fmaf(kv.z,a1.z, fmaf(kv.w,a1.w, acc.y))));
                    acc.z = fmaf(kv.x,a2.x, fmaf(kv.y,a2.y, fmaf(kv.z,a2.z, fmaf(kv.w,a2.w, acc.z))));
                    acc.w = fmaf(kv.x,a3.x, fmaf(kv.y,a3.y, fmaf(kv.z,a3.z, fmaf(kv.w,a3.w, acc.w))));
                }
                if (msk[qq*48 + k] != 0.f) acc = make_float4(-1e9f, -1e9f, -1e9f, -1e9f);
                *(float4*)&sb[qq*192 + k*4] = acc;
            }
        }
        BAR64(bid);

        // P5: softmax over k per head (16 lanes per head), both queries
        {
            const int h = lane >> 4, j = lane & 15;
            #pragma unroll
            for (int qq = 0; qq < QPS; qq++) {
                if (!v[qq]) continue;
                float* sq = sb + qq*192;
                float v0 = sq[j*4+h], v1 = sq[(j+16)*4+h], v2 = sq[(j+32)*4+h];
                float mx = fmaxf(v0, fmaxf(v1, v2));
                #pragma unroll
                for (int off = 8; off; off >>= 1)
                    mx = fmaxf(mx, __shfl_xor_sync(0xffffffffu, mx, off));
                float e0 = __expf(v0-mx), e1 = __expf(v1-mx), e2 = __expf(v2-mx);
                sq[j*4+h] = e0; sq[(j+16)*4+h] = e1; sq[(j+32)*4+h] = e2;
                float s = e0 + e1 + e2;
                #pragma unroll
                for (int off = 8; off; off >>= 1)
                    s += __shfl_xor_sync(0xffffffffu, s, off);
                if (j == 0) inv[qq*4 + h] = 1.0f / s;
            }
        }
        BAR64(bid);

        // P6: ctx[h,c] = sum_k a[h,k] k_in[k,c], both queries
        #pragma unroll
        for (int qq = 0; qq < QPS; qq++) {
            if (!v[qq]) continue;
            const float* kinq = kin + qq*KINQ;
            const float* sq = sb + qq*192;
            float a0=0.f, a1=0.f, a2=0.f, a3=0.f;
            #pragma unroll 8
            for (int k = 0; k < K_; k++) {
                float4 e = *(const float4*)&sq[k*4];
                float kv = kinq[k*KSTR + lane];
                a0 = fmaf(e.x, kv, a0); a1 = fmaf(e.y, kv, a1);
                a2 = fmaf(e.z, kv, a2); a3 = fmaf(e.w, kv, a3);
            }
            float* cq = ctx + qq*272;
            cq[0*CTXSTR+lane] = a0*inv[qq*4+0];
            cq[1*CTXSTR+lane] = a1*inv[qq*4+1];
            cq[2*CTXSTR+lane] = a2*inv[qq*4+2];
            cq[3*CTXSTR+lane] = a3*inv[qq*4+3];
        }
        BAR64(bid);

        // P7: o = ctx @ wv^T + bv — weight read shared by 2 queries
        {
            const int hrow = (lane >> 4) * CTXSTR;
            const float4* cr0 = (const float4*)(ctx + hrow);
            const float4* cr1 = (const float4*)(ctx + 272 + hrow);
            float a0 = sm[O_BV + lane], a1 = a0;
            #pragma unroll 4
            for (int c4 = 0; c4 < 16; c4++) {
                float4 cv0 = cr0[c4];
                float4 cv1 = cr1[c4];
                float w0 = sm[O_WVT + (c4*4+0)*64 + lane];
                float w1 = sm[O_WVT + (c4*4+1)*64 + lane];
                float w2 = sm[O_WVT + (c4*4+2)*64 + lane];
                float w3 = sm[O_WVT + (c4*4+3)*64 + lane];
                a0 = fmaf(cv0.x,w0, fmaf(cv0.y,w1, fmaf(cv0.z,w2, fmaf(cv0.w,w3, a0))));
                a1 = fmaf(cv1.x,w0, fmaf(cv1.y,w1, fmaf(cv1.z,w2, fmaf(cv1.w,w3, a1))));
            }
            if (v[0]) g_obuf[(qb+0)*64 + lane] = a0;
            if (v[1]) g_obuf[(qb+1)*64 + lane] = a1;
        }
    }
}

// ============================================================================
// ffn: out_proj + FFN + BN1 + output layer + BN2 + ReLU (unchanged structure)
// 4 groups x 128 threads (c, half), 8 queries per group per tile.
// ============================================================================
__global__ __launch_bounds__(512, 1) void ffn_kernel(
    const float* __restrict__ opw, const float* __restrict__ opb,
    const float* __restrict__ w1,  const float* __restrict__ b1,
    const float* __restrict__ w2,  const float* __restrict__ b2,
    const float* __restrict__ ng,  const float* __restrict__ nb,
    const float* __restrict__ nm,  const float* __restrict__ nv,
    const float* __restrict__ ow,  const float* __restrict__ ob,
    const float* __restrict__ g2,  const float* __restrict__ b2n,
    const float* __restrict__ m2,  const float* __restrict__ v2,
    float* __restrict__ out, int m)
{
    extern __shared__ float sm[];
    const int tid = threadIdx.x;

    for (int i = tid; i < 4096; i += 512) {
        int c = i & 63, cp = i >> 6;
        sm[Q_WOT  + i] = opw[c*64 + cp];
        sm[Q_WOUT + i] = ow[c*64 + cp];
    }
    for (int i = tid; i < 16384; i += 512) {
        sm[Q_W1T + i] = w1[(i & 255)*64 + (i >> 8)];
        sm[Q_W2T + i] = w2[(i & 63)*256 + (i >> 6)];
    }
    if (tid < 64) {
        sm[Q_BO + tid] = opb[tid];
        sm[Q_B2 + tid] = b2[tid];
        sm[Q_OUTB + tid] = ob[tid];
        float s1 = ng[tid] * rsqrtf(nv[tid] + 1e-5f);
        sm[Q_BN1S + tid] = s1;
        sm[Q_BN1T + tid] = nb[tid] - nm[tid] * s1;
        float s2 = g2[tid] * rsqrtf(v2[tid] + 1e-5f);
        sm[Q_BN2S + tid] = s2;
        sm[Q_BN2T + tid] = b2n[tid] - m2[tid] * s2;
    }
    if (tid < 256) sm[Q_B1 + tid] = b1[tid];
    __syncthreads();

    const int g = tid >> 7;
    const int t = tid & 127;
    const int c = t & 63;
    const int half = t >> 6;
    const int bid = g + 1;
    const int jb = half * 4;
    float* G    = sm + Q_GRP + g * GRP_FL;
    float* o8   = G;
    float* att8 = G + 512;
    float* h8   = G + 1024;

    const float bo_ = sm[Q_BO + c];
    const float bb2 = sm[Q_B2 + c];
    const float s1 = sm[Q_BN1S + c], t1 = sm[Q_BN1T + c];
    const float obc = sm[Q_OUTB + c], s2 = sm[Q_BN2S + c], t2 = sm[Q_BN2T + c];
    const int f0 = half * 128 + c, f1 = f0 + 64;
    const float b1a = sm[Q_B1 + f0], b1b = sm[Q_B1 + f1];

    for (int qb = blockIdx.x * 32; qb < m; qb += gridDim.x * 32) {
        const int qg = qb + g * 8;

        float4 ov;
        ov.x = (qg+jb+0 < m) ? g_obuf[(qg+jb+0)*64 + c] : 0.f;
        ov.y = (qg+jb+1 < m) ? g_obuf[(qg+jb+1)*64 + c] : 0.f;
        ov.z = (qg+jb+2 < m) ? g_obuf[(qg+jb+2)*64 + c] : 0.f;
        ov.w = (qg+jb+3 < m) ? g_obuf[(qg+jb+3)*64 + c] : 0.f;
        *(float4*)&o8[c*8 + jb] = ov;
        BAR128(bid);

        float4 att = make_float4(bo_, bo_, bo_, bo_);
        #pragma unroll 8
        for (int cp = 0; cp < 64; cp++) {
            float w = sm[Q_WOT + cp*64 + c];
            float4 a = *(const float4*)&o8[cp*8 + jb];
            att.x = fmaf(a.x,w,att.x); att.y = fmaf(a.y,w,att.y);
            att.z = fmaf(a.z,w,att.z); att.w = fmaf(a.w,w,att.w);
        }
        *(float4*)&att8[c*8 + jb] = att;
        BAR128(bid);

        float h0[8], h1[8];
        #pragma unroll
        for (int j = 0; j < 8; j++) { h0[j] = b1a; h1[j] = b1b; }
        #pragma unroll 4
        for (int cp = 0; cp < 64; cp++) {
            float w0 = sm[Q_W1T + cp*256 + f0];
            float w1_ = sm[Q_W1T + cp*256 + f1];
            float4 alo = *(const float4*)&att8[cp*8];
            float4 ahi = *(const float4*)&att8[cp*8+4];
            h0[0]=fmaf(alo.x,w0,h0[0]); h0[1]=fmaf(alo.y,w0,h0[1]);
            h0[2]=fmaf(alo.z,w0,h0[2]); h0[3]=fmaf(alo.w,w0,h0[3]);
            h0[4]=fmaf(ahi.x,w0,h0[4]); h0[5]=fmaf(ahi.y,w0,h0[5]);
            h0[6]=fmaf(ahi.z,w0,h0[6]); h0[7]=fmaf(ahi.w,w0,h0[7]);
            h1[0]=fmaf(alo.x,w1_,h1[0]); h1[1]=fmaf(alo.y,w1_,h1[1]);
            h1[2]=fmaf(alo.z,w1_,h1[2]); h1[3]=fmaf(alo.w,w1_,h1[3]);
            h1[4]=fmaf(ahi.x,w1_,h1[4]); h1[5]=fmaf(ahi.y,w1_,h1[5]);
            h1[6]=fmaf(ahi.z,w1_,h1[6]); h1[7]=fmaf(ahi.w,w1_,h1[7]);
        }
        #pragma unroll
        for (int j = 0; j < 8; j++) { h0[j] = fmaxf(h0[j],0.f); h1[j] = fmaxf(h1[j],0.f); }
        *(float4*)&h8[f0*8]   = make_float4(h0[0],h0[1],h0[2],h0[3]);
        *(float4*)&h8[f0*8+4] = make_float4(h0[4],h0[5],h0[6],h0[7]);
        *(float4*)&h8[f1*8]   = make_float4(h1[0],h1[1],h1[2],h1[3]);
        *(float4*)&h8[f1*8+4] = make_float4(h1[4],h1[5],h1[6],h1[7]);
        BAR128(bid);

        float x[8];
        if (half == 0) {
            float4 alo = *(const float4*)&att8[c*8];
            float4 ahi = *(const float4*)&att8[c*8+4];
            x[0]=alo.x+bb2; x[1]=alo.y+bb2; x[2]=alo.z+bb2; x[3]=alo.w+bb2;
            x[4]=ahi.x+bb2; x[5]=ahi.y+bb2; x[6]=ahi.z+bb2; x[7]=ahi.w+bb2;
        } else {
            #pragma unroll
            for (int j = 0; j < 8; j++) x[j] = 0.f;
        }
        {
            const int fb = half * 128;
            #pragma unroll 4
            for (int fl = 0; fl < 128; fl++) {
                const int f = fb + fl;
                float w = sm[Q_W2T + f*64 + c];
                float4 hlo = *(const float4*)&h8[f*8];
                float4 hhi = *(const float4*)&h8[f*8+4];
                x[0]=fmaf(hlo.x,w,x[0]); x[1]=fmaf(hlo.y,w,x[1]);
                x[2]=fmaf(hlo.z,w,x[2]); x[3]=fmaf(hlo.w,w,x[3]);
                x[4]=fmaf(hhi.x,w,x[4]); x[5]=fmaf(hhi.y,w,x[5]);
                x[6]=fmaf(hhi.z,w,x[6]); x[7]=fmaf(hhi.w,w,x[7]);
            }
        }
        if (half == 1) {
            *(float4*)&o8[c*8]   = make_float4(x[0],x[1],x[2],x[3]);
            *(float4*)&o8[c*8+4] = make_float4(x[4],x[5],x[6],x[7]);
        }
        BAR128(bid);
        if (half == 0) {
            float4 plo = *(const float4*)&o8[c*8];
            float4 phi = *(const float4*)&o8[c*8+4];
            x[0]+=plo.x; x[1]+=plo.y; x[2]+=plo.z; x[3]+=plo.w;
            x[4]+=phi.x; x[5]+=phi.y; x[6]+=phi.z; x[7]+=phi.w;
            #pragma unroll
            for (int j = 0; j < 8; j++) x[j] = fmaf(x[j], s1, t1);
            *(float4*)&h8[c*8]   = make_float4(x[0],x[1],x[2],x[3]);
            *(float4*)&h8[c*8+4] = make_float4(x[4],x[5],x[6],x[7]);
        }
        BAR128(bid);

        float4 y = make_float4(0.f,0.f,0.f,0.f);
        #pragma unroll 8
        for (int cp = 0; cp < 64; cp++) {
            float w = sm[Q_WOUT + cp*64 + c];
            float4 xv = *(const float4*)&h8[cp*8 + jb];
            y.x = fmaf(xv.x,w,y.x); y.y = fmaf(xv.y,w,y.y);
            y.z = fmaf(xv.z,w,y.z); y.w = fmaf(xv.w,w,y.w);
        }
        y.x = fmaxf(fmaf(y.x+obc, s2, t2), 0.f);
        y.y = fmaxf(fmaf(y.y+obc, s2, t2), 0.f);
        y.z = fmaxf(fmaf(y.z+obc, s2, t2), 0.f);
        y.w = fmaxf(fmaf(y.w+obc, s2, t2), 0.f);
        if (qg+jb+0 < m) out[(qg+jb+0)*64 + c] = y.x;
        if (qg+jb+1 < m) out[(qg+jb+1)*64 + c] = y.y;
        if (qg+jb+2 < m) out[(qg+jb+2)*64 + c] = y.z;
        if (qg+jb+3 < m) out[(qg+jb+3)*64 + c] = y.w;
        BAR128(bid);
    }
}

extern "C" void kernel_launch(void* const* d_in, const int* in_sizes, int n_in,
                              void* d_out, int out_size)
{
    const float* vf  = (const float*)d_in[0];
    const float* vc  = (const float*)d_in[1];
    const float* qc  = (const float*)d_in[2];
    const int*   ki  = (const int*)d_in[3];
    const void*  km  = d_in[4];
    const float* qpw = (const float*)d_in[5];
    const float* qpb = (const float*)d_in[6];
    const float* kpw = (const float*)d_in[7];
    const float* kpb = (const float*)d_in[8];
    const float* ipw = (const float*)d_in[9];
    const float* ipb = (const float*)d_in[10];
    const float* opw = (const float*)d_in[11];
    const float* opb = (const float*)d_in[12];
    const float* w1  = (const float*)d_in[13];
    const float* b1  = (const float*)d_in[14];
    const float* w2  = (const float*)d_in[15];
    const float* b2  = (const float*)d_in[16];
    const float* ng  = (const float*)d_in[17];
    const float* nb  = (const float*)d_in[18];
    const float* nm  = (const float*)d_in[19];
    const float* nv  = (const float*)d_in[20];
    const float* ow  = (const float*)d_in[21];
    const float* ob  = (const float*)d_in[22];
    const float* g2  = (const float*)d_in[23];
    const float* b2n = (const float*)d_in[24];
    const float* m2  = (const float*)d_in[25];
    const float* v2  = (const float*)d_in[26];

    int m = in_sizes[2] / 3;
    if (m > MQ_MAX) m = MQ_MAX;

    cudaFuncSetAttribute(attn_kernel, cudaFuncAttributeMaxDynamicSharedMemorySize, SMEM1_BYTES);
    cudaFuncSetAttribute(ffn_kernel, cudaFuncAttributeMaxDynamicSharedMemorySize, SMEM2_BYTES);

    attn_kernel<<<148, THREADS1, SMEM1_BYTES>>>(vf, vc, qc, ki, km, qpw, qpb, kpw, kpb,
                                                ipw, ipb, m, (float*)d_out, (long long)out_size);
    ffn_kernel<<<148, 512, SMEM2_BYTES>>>(opw, opb, w1, b1, w2, b2, ng, nb, nm, nv,
                                          ow, ob, g2, b2n, m2, v2, (float*)d_out, m);
}

// round 15
// speedup vs baseline: 1.1016x; 1.1016x over previous
#include <cuda_runtime.h>

constexpr int C_ = 64, K_ = 48, MQ_MAX = 25000;
constexpr int NSLOT = 10, THREADS1 = NSLOT * 64;          // 640
constexpr int KSTR = 66, CTXSTR = 68;

// kernel1 smem offsets (floats)
constexpr int O_WQT=0, O_WK=4096, O_WVT=8192, O_BQ=12288, O_BV=12352,
  O_QPW=12416, O_QPB=12608, O_KPW=12672, O_KPB=12864, O_SLOT=12928;
constexpr int S_KIN=0, S_U=3168, S_QV=3424, S_QIN=3488, S_SB=3552, S_CTX=3744,
  S_REL4=4016, S_MSK=4208, S_KIX=4256, S_INV=4304, SLOT_FL=4256+52;  // 4308->pad to 4256? keep 4256+52
constexpr int SLOT_FL_ = 4308;
constexpr int SMEM1_BYTES = (O_SLOT + NSLOT*SLOT_FL_) * 4;  // 224032 B

// kernel2 smem offsets (floats) — 4 groups x 128 threads, Q8
constexpr int Q_WOT=0, Q_W1T=4096, Q_W2T=20480, Q_WOUT=36864, Q_BO=40960,
  Q_B1=41024, Q_B2=41280, Q_BN1S=41344, Q_BN1T=41408, Q_BN2S=41472,
  Q_BN2T=41536, Q_OUTB=41600, Q_GRP=41664, GRP_FL=3072;
constexpr int SMEM2_BYTES = (Q_GRP + 4*GRP_FL) * 4;        // 215808

__device__ float g_obuf[MQ_MAX * C_];

#define BAR64(id)  asm volatile("bar.sync %0, 64;"  :: "r"(id) : "memory")
#define BAR128(id) asm volatile("bar.sync %0, 128;" :: "r"(id) : "memory")

// Block-local detection of key_mask storage: 0=uint8, 1=int32, 2=float32.
__device__ __forceinline__ int detect_mask_mode(const unsigned char* __restrict__ b,
                                                int* scratch, int tid, int nthr) {
    unsigned my123 = 0, my3f = 0;
    for (int i = tid * 8; i < tid * 8 + 8; i++) {
        if (i < 4096) {
            unsigned v = b[i];
            if ((i & 3) && v) my123 = 1;
            if ((i & 3) == 3 && v == 0x3fu) my3f = 1;
        }
    }
    unsigned w123 = __ballot_sync(0xffffffffu, my123 != 0);
    unsigned w3f  = __ballot_sync(0xffffffffu, my3f  != 0);
    int nw = nthr >> 5;
    if ((tid & 31) == 0) {
        scratch[(tid >> 5) * 2 + 0] = (w123 != 0);
        scratch[(tid >> 5) * 2 + 1] = (w3f  != 0);
    }
    __syncthreads();
    if (tid == 0) {
        int a123 = 0, a3f = 0;
        for (int w = 0; w < nw; w++) { a123 |= scratch[w*2]; a3f |= scratch[w*2+1]; }
        scratch[64] = (a123 == 0) ? 1 : (a3f ? 2 : 0);
    }
    __syncthreads();
    int mode = scratch[64];
    __syncthreads();
    return mode;
}

// ============================================================================
// attn: gather + pos-proj + restructured MHA -> g_obuf (+ d_out tail zero)
// 10 slots x 64 lanes (20 warps/SM); per-slot named barriers.
// ============================================================================
__global__ __launch_bounds__(THREADS1, 1) void attn_kernel(
    const float* __restrict__ vf, const float* __restrict__ vcoord,
    const float* __restrict__ qcoord, const int* __restrict__ kidx,
    const void* __restrict__ kmask,
    const float* __restrict__ qpw_g, const float* __restrict__ qpb_g,
    const float* __restrict__ kpw_g, const float* __restrict__ kpb_g,
    const float* __restrict__ ipW, const float* __restrict__ ipB, int m,
    float* __restrict__ out, long long out_size)
{
    extern __shared__ float sm[];
    const int tid = threadIdx.x;

    // zero d_out tail beyond m*64 (poison insurance; attn precedes ffn in-stream)
    for (long long i = (long long)m * 64 + (long long)blockIdx.x * blockDim.x + tid;
         i < out_size; i += (long long)gridDim.x * blockDim.x)
        out[i] = 0.f;

    for (int i = tid; i < 4096; i += THREADS1) {
        int c = i & 63, cp = i >> 6;
        sm[O_WQT + i] = ipW[c * 64 + cp];           // wq^T
        sm[O_WK  + i] = ipW[4096 + i];              // wk row-major
        sm[O_WVT + i] = ipW[(128 + c) * 64 + cp];   // wv^T
    }
    if (tid < 64) {
        sm[O_BQ + tid] = ipB[tid];
        sm[O_BV + tid] = ipB[128 + tid];
        sm[O_QPB + tid] = qpb_g[tid];
        sm[O_KPB + tid] = kpb_g[tid];
    }
    if (tid < 192) { sm[O_QPW + tid] = qpw_g[tid]; sm[O_KPW + tid] = kpw_g[tid]; }
    __syncthreads();

    const int mode = detect_mask_mode((const unsigned char*)kmask,
                                      (int*)(sm + O_SLOT), tid, THREADS1);

    const int slot = tid >> 6, lane = tid & 63;
    const int bid = slot + 1;
    float* S = sm + O_SLOT + slot * SLOT_FL_;
    float* kin = S + S_KIN;  float* u_s = S + S_U;   float* qv_s = S + S_QV;
    float* qin_s = S + S_QIN; float* sb = S + S_SB;  float* ctx = S + S_CTX;
    float4* rel4 = (float4*)(S + S_REL4);
    float* msk = S + S_MSK;  int* kix = (int*)(S + S_KIX);
    float* inv = S + S_INV;

    const float kw0 = sm[O_KPW + lane*3+0], kw1 = sm[O_KPW + lane*3+1],
                kw2 = sm[O_KPW + lane*3+2], kb_ = sm[O_KPB + lane];

    const int step = gridDim.x * NSLOT;

    float nc0, nc1, nc2, nmv = 0.f, nvx = 0.f, nvy = 0.f, nvz = 0.f;
    int nvi = 0;
    {
        int qn = blockIdx.x * NSLOT + slot;
        int qc_ = (qn < m) ? qn : 0;
        nc0 = __ldg(&qcoord[qc_*3+0]);
        nc1 = __ldg(&qcoord[qc_*3+1]);
        nc2 = __ldg(&qcoord[qc_*3+2]);
        if (lane < K_) {
            const int idx = qc_ * K_ + lane;
            nvi = __ldg(&kidx[idx]);
            if (mode == 0)      nmv = ((const unsigned char*)kmask)[idx] ? 1.f : 0.f;
            else if (mode == 1) nmv = ((const int*)kmask)[idx] ? 1.f : 0.f;
            else                nmv = (((const float*)kmask)[idx] != 0.f) ? 1.f : 0.f;
            nvx = __ldg(&vcoord[nvi*3+0]);
            nvy = __ldg(&vcoord[nvi*3+1]);
            nvz = __ldg(&vcoord[nvi*3+2]);
        }
    }

    for (int q0 = blockIdx.x * NSLOT; q0 < m; q0 += step) {
        const int q = q0 + slot;
        const bool valid = (q < m);

        if (valid) {   // P01: consume prefetched data
            const float c0 = nc0, c1 = nc1, c2 = nc2;
            if (lane < K_) {
                msk[lane] = nmv;
                kix[lane] = nvi;
                float4 r;
                r.x = nvx - c0; r.y = nvy - c1; r.z = nvz - c2; r.w = 0.f;
                rel4[lane] = r;
            }
            float t = sm[O_QPB + lane];
            t = fmaf(sm[O_QPW + lane*3+0], c0, t);
            t = fmaf(sm[O_QPW + lane*3+1], c1, t);
            t = fmaf(sm[O_QPW + lane*3+2], c2, t);
            qin_s[lane] = fmaxf(t, 0.f);
        }
        {   // prefetch next query's data
            int qn = q + step;
            int qc_ = (qn < m) ? qn : 0;
            nc0 = __ldg(&qcoord[qc_*3+0]);
            nc1 = __ldg(&qcoord[qc_*3+1]);
            nc2 = __ldg(&qcoord[qc_*3+2]);
            if (lane < K_) {
                const int idx = qc_ * K_ + lane;
                nvi = __ldg(&kidx[idx]);
                if (mode == 0)      nmv = ((const unsigned char*)kmask)[idx] ? 1.f : 0.f;
                else if (mode == 1) nmv = ((const int*)kmask)[idx] ? 1.f : 0.f;
                else                nmv = (((const float*)kmask)[idx] != 0.f) ? 1.f : 0.f;
                nvx = __ldg(&vcoord[nvi*3+0]);
                nvy = __ldg(&vcoord[nvi*3+1]);
                nvz = __ldg(&vcoord[nvi*3+2]);
            }
        }
        BAR64(bid);

        if (valid) {   // P2: q = (q_in @ wq^T + bq) * d^-0.5
            float acc = sm[O_BQ + lane];
            #pragma unroll
            for (int cp = 0; cp < 64; cp += 4) {
                float4 a = *(const float4*)&qin_s[cp];
                acc = fmaf(a.x, sm[O_WQT + (cp+0)*64 + lane], acc);
                acc = fmaf(a.y, sm[O_WQT + (cp+1)*64 + lane], acc);
                acc = fmaf(a.z, sm[O_WQT + (cp+2)*64 + lane], acc);
                acc = fmaf(a.w, sm[O_WQT + (cp+3)*64 + lane], acc);
            }
            qv_s[lane] = acc * 0.25f;
        }
        BAR64(bid);

        if (valid) {   // P3: u[h] = wk_h^T @ q_h ; gather k_in (16 LDG in flight)
            #pragma unroll
            for (int h = 0; h < 4; h++) {
                float acc = 0.f;
                #pragma unroll
                for (int j4 = 0; j4 < 4; j4++) {
                    float4 qv = *(const float4*)&qv_s[h*16 + j4*4];
                    acc = fmaf(sm[O_WK + (h*16+j4*4+0)*64 + lane], qv.x, acc);
                    acc = fmaf(sm[O_WK + (h*16+j4*4+1)*64 + lane], qv.y, acc);
                    acc = fmaf(sm[O_WK + (h*16+j4*4+2)*64 + lane], qv.z, acc);
                    acc = fmaf(sm[O_WK + (h*16+j4*4+3)*64 + lane], qv.w, acc);
                }
                u_s[h*64 + lane] = acc;
            }
            #pragma unroll
            for (int kb = 0; kb < K_; kb += 16) {
                float fv[16];
                #pragma unroll
                for (int j = 0; j < 16; j++)
                    fv[j] = __ldg(&vf[kix[kb+j] * 64 + lane]);
                #pragma unroll
                for (int j = 0; j < 16; j++) {
                    float4 r = rel4[kb+j];
                    float kp = kb_;
                    kp = fmaf(kw0, r.x, kp);
                    kp = fmaf(kw1, r.y, kp);
                    kp = fmaf(kw2, r.z, kp);
                    kin[(kb+j)*KSTR + lane] = fv[j] + fmaxf(kp, 0.f);
                }
            }
        }
        BAR64(bid);

        if (valid && lane < K_) {   // P4: scores — lane = key, all 4 heads
            const int k = lane;
            const float2* kr = (const float2*)&kin[k*KSTR];
            const float4* u4 = (const float4*)u_s;
            float4 acc = make_float4(0.f, 0.f, 0.f, 0.f);
            #pragma unroll 4
            for (int c4 = 0; c4 < 16; c4++) {
                float2 ka = kr[2*c4], kc = kr[2*c4+1];
                float4 a0 = u4[c4], a1 = u4[16+c4], a2 = u4[32+c4], a3 = u4[48+c4];
                acc.x = fmaf(ka.x,a0.x, fmaf(ka.y,a0.y, fmaf(kc.x,a0.z, fmaf(kc.y,a0.w, acc.x))));
                acc.y = fmaf(ka.x,a1.x, fmaf(ka.y,a1.y, fmaf(kc.x,a1.z, fmaf(kc.y,a1.w, acc.y))));
                acc.z = fmaf(ka.x,a2.x, fmaf(ka.y,a2.y, fmaf(kc.x,a2.z, fmaf(kc.y,a2.w, acc.z))));
                acc.w = fmaf(ka.x,a3.x, fmaf(ka.y,a3.y, fmaf(kc.x,a3.z, fmaf(kc.y,a3.w, acc.w))));
            }
            if (msk[k] != 0.f) acc = make_float4(-1e9f, -1e9f, -1e9f, -1e9f);
            *(float4*)&sb[k*4] = acc;
        }
        BAR64(bid);

        if (valid) {   // P5: softmax
            const int h = lane >> 4, j = lane & 15;
            float v0 = sb[j*4+h], v1 = sb[(j+16)*4+h], v2 = sb[(j+32)*4+h];
            float mx = fmaxf(v0, fmaxf(v1, v2));
            #pragma unroll
            for (int off = 8; off; off >>= 1)
                mx = fmaxf(mx, __shfl_xor_sync(0xffffffffu, mx, off));
            float e0 = __expf(v0-mx), e1 = __expf(v1-mx), e2 = __expf(v2-mx);
            sb[j*4+h] = e0; sb[(j+16)*4+h] = e1; sb[(j+32)*4+h] = e2;
            float s = e0 + e1 + e2;
            #pragma unroll
            for (int off = 8; off; off >>= 1)
                s += __shfl_xor_sync(0xffffffffu, s, off);
            if (j == 0) inv[h] = 1.0f / s;
        }
        BAR64(bid);

        if (valid) {   // P6: ctx[h,c] = sum_k a[h,k] k_in[k,c]
            float a0=0.f, a1=0.f, a2=0.f, a3=0.f;
            #pragma unroll 8
            for (int k = 0; k < K_; k++) {
                float4 e = *(const float4*)&sb[k*4];
                float kv = kin[k*KSTR + lane];
                a0 = fmaf(e.x, kv, a0); a1 = fmaf(e.y, kv, a1);
                a2 = fmaf(e.z, kv, a2); a3 = fmaf(e.w, kv, a3);
            }
            ctx[0*CTXSTR+lane] = a0*inv[0]; ctx[1*CTXSTR+lane] = a1*inv[1];
            ctx[2*CTXSTR+lane] = a2*inv[2]; ctx[3*CTXSTR+lane] = a3*inv[3];
        }
        BAR64(bid);

        if (valid) {   // P7: o = ctx @ wv^T + bv -> global
            const float4* cr4 = (const float4*)(ctx + (lane >> 4) * CTXSTR);
            float acc = sm[O_BV + lane];
            #pragma unroll 4
            for (int c4 = 0; c4 < 16; c4++) {
                float4 cv = cr4[c4];
                acc = fmaf(cv.x, sm[O_WVT + (c4*4+0)*64 + lane], acc);
                acc = fmaf(cv.y, sm[O_WVT + (c4*4+1)*64 + lane], acc);
                acc = fmaf(cv.z, sm[O_WVT + (c4*4+2)*64 + lane], acc);
                acc = fmaf(cv.w, sm[O_WVT + (c4*4+3)*64 + lane], acc);
            }
            g_obuf[q*64 + lane] = acc;
        }
    }
}

// ============================================================================
// ffn: out_proj + FFN + BN1 + output layer + BN2 + ReLU
// 4 groups x 128 threads (c, half), 8 queries per group per tile.
// ============================================================================
__global__ __launch_bounds__(512, 1) void ffn_kernel(
    const float* __restrict__ opw, const float* __restrict__ opb,
    const float* __restrict__ w1,  const float* __restrict__ b1,
    const float* __restrict__ w2,  const float* __restrict__ b2,
    const float* __restrict__ ng,  const float* __restrict__ nb,
    const float* __restrict__ nm,  const float* __restrict__ nv,
    const float* __restrict__ ow,  const float* __restrict__ ob,
    const float* __restrict__ g2,  const float* __restrict__ b2n,
    const float* __restrict__ m2,  const float* __restrict__ v2,
    float* __restrict__ out, int m)
{
    extern __shared__ float sm[];
    const int tid = threadIdx.x;

    for (int i = tid; i < 4096; i += 512) {
        int c = i & 63, cp = i >> 6;
        sm[Q_WOT  + i] = opw[c*64 + cp];
        sm[Q_WOUT + i] = ow[c*64 + cp];
    }
    for (int i = tid; i < 16384; i += 512) {
        sm[Q_W1T + i] = w1[(i & 255)*64 + (i >> 8)];
        sm[Q_W2T + i] = w2[(i & 63)*256 + (i >> 6)];
    }
    if (tid < 64) {
        sm[Q_BO + tid] = opb[tid];
        sm[Q_B2 + tid] = b2[tid];
        sm[Q_OUTB + tid] = ob[tid];
        float s1 = ng[tid] * rsqrtf(nv[tid] + 1e-5f);
        sm[Q_BN1S + tid] = s1;
        sm[Q_BN1T + tid] = nb[tid] - nm[tid] * s1;
        float s2 = g2[tid] * rsqrtf(v2[tid] + 1e-5f);
        sm[Q_BN2S + tid] = s2;
        sm[Q_BN2T + tid] = b2n[tid] - m2[tid] * s2;
    }
    if (tid < 256) sm[Q_B1 + tid] = b1[tid];
    __syncthreads();

    const int g = tid >> 7;
    const int t = tid & 127;
    const int c = t & 63;
    const int half = t >> 6;
    const int bid = g + 1;
    const int jb = half * 4;
    float* G    = sm + Q_GRP + g * GRP_FL;
    float* o8   = G;
    float* att8 = G + 512;
    float* h8   = G + 1024;

    const float bo_ = sm[Q_BO + c];
    const float bb2 = sm[Q_B2 + c];
    const float s1 = sm[Q_BN1S + c], t1 = sm[Q_BN1T + c];
    const float obc = sm[Q_OUTB + c], s2 = sm[Q_BN2S + c], t2 = sm[Q_BN2T + c];
    const int f0 = half * 128 + c, f1 = f0 + 64;
    const float b1a = sm[Q_B1 + f0], b1b = sm[Q_B1 + f1];

    for (int qb = blockIdx.x * 32; qb < m; qb += gridDim.x * 32) {
        const int qg = qb + g * 8;

        float4 ov;
        ov.x = (qg+jb+0 < m) ? g_obuf[(qg+jb+0)*64 + c] : 0.f;
        ov.y = (qg+jb+1 < m) ? g_obuf[(qg+jb+1)*64 + c] : 0.f;
        ov.z = (qg+jb+2 < m) ? g_obuf[(qg+jb+2)*64 + c] : 0.f;
        ov.w = (qg+jb+3 < m) ? g_obuf[(qg+jb+3)*64 + c] : 0.f;
        *(float4*)&o8[c*8 + jb] = ov;
        BAR128(bid);

        float4 att = make_float4(bo_, bo_, bo_, bo_);
        #pragma unroll 8
        for (int cp = 0; cp < 64; cp++) {
            float w = sm[Q_WOT + cp*64 + c];
            float4 a = *(const float4*)&o8[cp*8 + jb];
            att.x = fmaf(a.x,w,att.x); att.y = fmaf(a.y,w,att.y);
            att.z = fmaf(a.z,w,att.z); att.w = fmaf(a.w,w,att.w);
        }
        *(float4*)&att8[c*8 + jb] = att;
        BAR128(bid);

        float h0[8], h1[8];
        #pragma unroll
        for (int j = 0; j < 8; j++) { h0[j] = b1a; h1[j] = b1b; }
        #pragma unroll 4
        for (int cp = 0; cp < 64; cp++) {
            float w0 = sm[Q_W1T + cp*256 + f0];
            float w1_ = sm[Q_W1T + cp*256 + f1];
            float4 alo = *(const float4*)&att8[cp*8];
            float4 ahi = *(const float4*)&att8[cp*8+4];
            h0[0]=fmaf(alo.x,w0,h0[0]); h0[1]=fmaf(alo.y,w0,h0[1]);
            h0[2]=fmaf(alo.z,w0,h0[2]); h0[3]=fmaf(alo.w,w0,h0[3]);
            h0[4]=fmaf(ahi.x,w0,h0[4]); h0[5]=fmaf(ahi.y,w0,h0[5]);
            h0[6]=fmaf(ahi.z,w0,h0[6]); h0[7]=fmaf(ahi.w,w0,h0[7]);
            h1[0]=fmaf(alo.x,w1_,h1[0]); h1[1]=fmaf(alo.y,w1_,h1[1]);
            h1[2]=fmaf(alo.z,w1_,h1[2]); h1[3]=fmaf(alo.w,w1_,h1[3]);
            h1[4]=fmaf(ahi.x,w1_,h1[4]); h1[5]=fmaf(ahi.y,w1_,h1[5]);
            h1[6]=fmaf(ahi.z,w1_,h1[6]); h1[7]=fmaf(ahi.w,w1_,h1[7]);
        }
        #pragma unroll
        for (int j = 0; j < 8; j++) { h0[j] = fmaxf(h0[j],0.f); h1[j] = fmaxf(h1[j],0.f); }
        *(float4*)&h8[f0*8]   = make_float4(h0[0],h0[1],h0[2],h0[3]);
        *(float4*)&h8[f0*8+4] = make_float4(h0[4],h0[5],h0[6],h0[7]);
        *(float4*)&h8[f1*8]   = make_float4(h1[0],h1[1],h1[2],h1[3]);
        *(float4*)&h8[f1*8+4] = make_float4(h1[4],h1[5],h1[6],h1[7]);
        BAR128(bid);

        float x[8];
        if (half == 0) {
            float4 alo = *(const float4*)&att8[c*8];
            float4 ahi = *(const float4*)&att8[c*8+4];
            x[0]=alo.x+bb2; x[1]=alo.y+bb2; x[2]=alo.z+bb2; x[3]=alo.w+bb2;
            x[4]=ahi.x+bb2; x[5]=ahi.y+bb2; x[6]=ahi.z+bb2; x[7]=ahi.w+bb2;
        } else {
            #pragma unroll
            for (int j = 0; j < 8; j++) x[j] = 0.f;
        }
        {
            const int fb = half * 128;
            #pragma unroll 4
            for (int fl = 0; fl < 128; fl++) {
                const int f = fb + fl;
                float w = sm[Q_W2T + f*64 + c];
                float4 hlo = *(const float4*)&h8[f*8];
                float4 hhi = *(const float4*)&h8[f*8+4];
                x[0]=fmaf(hlo.x,w,x[0]); x[1]=fmaf(hlo.y,w,x[1]);
                x[2]=fmaf(hlo.z,w,x[2]); x[3]=fmaf(hlo.w,w,x[3]);
                x[4]=fmaf(hhi.x,w,x[4]); x[5]=fmaf(hhi.y,w,x[5]);
                x[6]=fmaf(hhi.z,w,x[6]); x[7]=fmaf(hhi.w,w,x[7]);
            }
        }
        if (half == 1) {
            *(float4*)&o8[c*8]   = make_float4(x[0],x[1],x[2],x[3]);
            *(float4*)&o8[c*8+4] = make_float4(x[4],x[5],x[6],x[7]);
        }
        BAR128(bid);
        if (half == 0) {
            float4 plo = *(const float4*)&o8[c*8];
            float4 phi = *(const float4*)&o8[c*8+4];
            x[0]+=plo.x; x[1]+=plo.y; x[2]+=plo.z; x[3]+=plo.w;
            x[4]+=phi.x; x[5]+=phi.y; x[6]+=phi.z; x[7]+=phi.w;
            #pragma unroll
            for (int j = 0; j < 8; j++) x[j] = fmaf(x[j], s1, t1);
            *(float4*)&h8[c*8]   = make_float4(x[0],x[1],x[2],x[3]);
            *(float4*)&h8[c*8+4] = make_float4(x[4],x[5],x[6],x[7]);
        }
        BAR128(bid);

        float4 y = make_float4(0.f,0.f,0.f,0.f);
        #pragma unroll 8
        for (int cp = 0; cp < 64; cp++) {
            float w = sm[Q_WOUT + cp*64 + c];
            float4 xv = *(const float4*)&h8[cp*8 + jb];
            y.x = fmaf(xv.x,w,y.x); y.y = fmaf(xv.y,w,y.y);
            y.z = fmaf(xv.z,w,y.z); y.w = fmaf(xv.w,w,y.w);
        }
        y.x = fmaxf(fmaf(y.x+obc, s2, t2), 0.f);
        y.y = fmaxf(fmaf(y.y+obc, s2, t2), 0.f);
        y.z = fmaxf(fmaf(y.z+obc, s2, t2), 0.f);
        y.w = fmaxf(fmaf(y.w+obc, s2, t2), 0.f);
        if (qg+jb+0 < m) out[(qg+jb+0)*64 + c] = y.x;
        if (qg+jb+1 < m) out[(qg+jb+1)*64 + c] = y.y;
        if (qg+jb+2 < m) out[(qg+jb+2)*64 + c] = y.z;
        if (qg+jb+3 < m) out[(qg+jb+3)*64 + c] = y.w;
        BAR128(bid);
    }
}

extern "C" void kernel_launch(void* const* d_in, const int* in_sizes, int n_in,
                              void* d_out, int out_size)
{
    const float* vf  = (const float*)d_in[0];
    const float* vc  = (const float*)d_in[1];
    const float* qc  = (const float*)d_in[2];
    const int*   ki  = (const int*)d_in[3];
    const void*  km  = d_in[4];
    const float* qpw = (const float*)d_in[5];
    const float* qpb = (const float*)d_in[6];
    const float* kpw = (const float*)d_in[7];
    const float* kpb = (const float*)d_in[8];
    const float* ipw = (const float*)d_in[9];
    const float* ipb = (const float*)d_in[10];
    const float* opw = (const float*)d_in[11];
    const float* opb = (const float*)d_in[12];
    const float* w1  = (const float*)d_in[13];
    const float* b1  = (const float*)d_in[14];
    const float* w2  = (const float*)d_in[15];
    const float* b2  = (const float*)d_in[16];
    const float* ng  = (const float*)d_in[17];
    const float* nb  = (const float*)d_in[18];
    const float* nm  = (const float*)d_in[19];
    const float* nv  = (const float*)d_in[20];
    const float* ow  = (const float*)d_in[21];
    const float* ob  = (const float*)d_in[22];
    const float* g2  = (const float*)d_in[23];
    const float* b2n = (const float*)d_in[24];
    const float* m2  = (const float*)d_in[25];
    const float* v2  = (const float*)d_in[26];

    int m = in_sizes[2] / 3;
    if (m > MQ_MAX) m = MQ_MAX;

    cudaFuncSetAttribute(attn_kernel, cudaFuncAttributeMaxDynamicSharedMemorySize, SMEM1_BYTES);
    cudaFuncSetAttribute(ffn_kernel, cudaFuncAttributeMaxDynamicSharedMemorySize, SMEM2_BYTES);

    attn_kernel<<<148, THREADS1, SMEM1_BYTES>>>(vf, vc, qc, ki, km, qpw, qpb, kpw, kpb,
                                                ipw, ipb, m, (float*)d_out, (long long)out_size);
    ffn_kernel<<<148, 512, SMEM2_BYTES>>>(opw, opb, w1, b1, w2, b2, ng, nb, nm, nv,
                                          ow, ob, g2, b2n, m2, v2, (float*)d_out, m);
}

// round 17
// speedup vs baseline: 1.1095x; 1.0071x over previous
#include <cuda_runtime.h>
#include <cuda_fp16.h>

constexpr int C_ = 64, K_ = 48, MQ_MAX = 25000;
constexpr int NSLOT = 10, THREADS1 = NSLOT * 64;          // 640
constexpr int CTXSTR = 68;

// kernel1 smem offsets (floats)
constexpr int O_WQT=0, O_WK=4096, O_WVT=8192, O_BQ=12288, O_BV=12352,
  O_QPW=12416, O_QPB=12608, O_KPW=12672, O_KPB=12864, O_SLOT=12928;
// per-slot offsets (floats). kin is fp16: 48 rows x 64 halfs = 6144B = 1536 fl.
constexpr int S_KINH=0, S_U=1536, S_QV=1792, S_QIN=1856, S_SB=1920, S_CTX=2112,
  S_REL4=2384, S_MSK=2576, S_KIX=2624, S_INV=2672, SLOT_FL=2680;
constexpr int SMEM1_BYTES = (O_SLOT + NSLOT*SLOT_FL) * 4;  // 158912 B

// kernel2 smem offsets (floats) — 4 groups x 128 threads, Q8 (unchanged)
constexpr int Q_WOT=0, Q_W1T=4096, Q_W2T=20480, Q_WOUT=36864, Q_BO=40960,
  Q_B1=41024, Q_B2=41280, Q_BN1S=41344, Q_BN1T=41408, Q_BN2S=41472,
  Q_BN2T=41536, Q_OUTB=41600, Q_GRP=41664, GRP_FL=3072;
constexpr int SMEM2_BYTES = (Q_GRP + 4*GRP_FL) * 4;        // 215808

__device__ float g_obuf[MQ_MAX * C_];

#define BAR64(id)  asm volatile("bar.sync %0, 64;"  :: "r"(id) : "memory")
#define BAR128(id) asm volatile("bar.sync %0, 128;" :: "r"(id) : "memory")

__device__ __forceinline__ float2 h2f(unsigned u) {
    __half2 h = *reinterpret_cast<__half2*>(&u);
    return __half22float2(h);
}

// Block-local detection of key_mask storage: 0=uint8, 1=int32, 2=float32.
__device__ __forceinline__ int detect_mask_mode(const unsigned char* __restrict__ b,
                                                int* scratch, int tid, int nthr) {
    unsigned my123 = 0, my3f = 0;
    for (int i = tid * 8; i < tid * 8 + 8; i++) {
        if (i < 4096) {
            unsigned v = b[i];
            if ((i & 3) && v) my123 = 1;
            if ((i & 3) == 3 && v == 0x3fu) my3f = 1;
        }
    }
    unsigned w123 = __ballot_sync(0xffffffffu, my123 != 0);
    unsigned w3f  = __ballot_sync(0xffffffffu, my3f  != 0);
    int nw = nthr >> 5;
    if ((tid & 31) == 0) {
        scratch[(tid >> 5) * 2 + 0] = (w123 != 0);
        scratch[(tid >> 5) * 2 + 1] = (w3f  != 0);
    }
    __syncthreads();
    if (tid == 0) {
        int a123 = 0, a3f = 0;
        for (int w = 0; w < nw; w++) { a123 |= scratch[w*2]; a3f |= scratch[w*2+1]; }
        scratch[64] = (a123 == 0) ? 1 : (a3f ? 2 : 0);
    }
    __syncthreads();
    int mode = scratch[64];
    __syncthreads();
    return mode;
}

// ============================================================================
// attn: gather + pos-proj + restructured MHA -> g_obuf (+ d_out tail zero)
// 10 slots x 64 lanes; kin in fp16 with 16B-unit XOR swizzle (conflict-free).
// ============================================================================
__global__ __launch_bounds__(THREADS1, 1) void attn_kernel(
    const float* __restrict__ vf, const float* __restrict__ vcoord,
    const float* __restrict__ qcoord, const int* __restrict__ kidx,
    const void* __restrict__ kmask,
    const float* __restrict__ qpw_g, const float* __restrict__ qpb_g,
    const float* __restrict__ kpw_g, const float* __restrict__ kpb_g,
    const float* __restrict__ ipW, const float* __restrict__ ipB, int m,
    float* __restrict__ out, long long out_size)
{
    extern __shared__ float sm[];
    const int tid = threadIdx.x;

    for (long long i = (long long)m * 64 + (long long)blockIdx.x * blockDim.x + tid;
         i < out_size; i += (long long)gridDim.x * blockDim.x)
        out[i] = 0.f;

    for (int i = tid; i < 4096; i += THREADS1) {
        int c = i & 63, cp = i >> 6;
        sm[O_WQT + i] = ipW[c * 64 + cp];           // wq^T
        sm[O_WK  + i] = ipW[4096 + i];              // wk row-major
        sm[O_WVT + i] = ipW[(128 + c) * 64 + cp];   // wv^T
    }
    if (tid < 64) {
        sm[O_BQ + tid] = ipB[tid];
        sm[O_BV + tid] = ipB[128 + tid];
        sm[O_QPB + tid] = qpb_g[tid];
        sm[O_KPB + tid] = kpb_g[tid];
    }
    if (tid < 192) { sm[O_QPW + tid] = qpw_g[tid]; sm[O_KPW + tid] = kpw_g[tid]; }
    __syncthreads();

    const int mode = detect_mask_mode((const unsigned char*)kmask,
                                      (int*)(sm + O_SLOT), tid, THREADS1);

    const int slot = tid >> 6, lane = tid & 63;
    const int bid = slot + 1;
    float* S = sm + O_SLOT + slot * SLOT_FL;
    __half* kinh = (__half*)(S + S_KINH);            // 48 x 64 halfs, XOR-swizzled
    char*   kinb = (char*)kinh;
    float* u_s = S + S_U;    float* qv_s = S + S_QV;
    float* qin_s = S + S_QIN; float* sb = S + S_SB;  float* ctx = S + S_CTX;
    float4* rel4 = (float4*)(S + S_REL4);
    float* msk = S + S_MSK;  int* kix = (int*)(S + S_KIX);
    float* inv = S + S_INV;

    const float kw0 = sm[O_KPW + lane*3+0], kw1 = sm[O_KPW + lane*3+1],
                kw2 = sm[O_KPW + lane*3+2], kb_ = sm[O_KPB + lane];
    const int lj = lane >> 3, lp = lane & 7;         // unit / pos for kin stores

    const int step = gridDim.x * NSLOT;

    float nc0, nc1, nc2, nmv = 0.f, nvx = 0.f, nvy = 0.f, nvz = 0.f;
    int nvi = 0;
    {
        int qn = blockIdx.x * NSLOT + slot;
        int qc_ = (qn < m) ? qn : 0;
        nc0 = __ldg(&qcoord[qc_*3+0]);
        nc1 = __ldg(&qcoord[qc_*3+1]);
        nc2 = __ldg(&qcoord[qc_*3+2]);
        if (lane < K_) {
            const int idx = qc_ * K_ + lane;
            nvi = __ldg(&kidx[idx]);
            if (mode == 0)      nmv = ((const unsigned char*)kmask)[idx] ? 1.f : 0.f;
            else if (mode == 1) nmv = ((const int*)kmask)[idx] ? 1.f : 0.f;
            else                nmv = (((const float*)kmask)[idx] != 0.f) ? 1.f : 0.f;
            nvx = __ldg(&vcoord[nvi*3+0]);
            nvy = __ldg(&vcoord[nvi*3+1]);
            nvz = __ldg(&vcoord[nvi*3+2]);
        }
    }

    for (int q0 = blockIdx.x * NSLOT; q0 < m; q0 += step) {
        const int q = q0 + slot;
        const bool valid = (q < m);

        if (valid) {   // P01: consume prefetched data
            const float c0 = nc0, c1 = nc1, c2 = nc2;
            if (lane < K_) {
                msk[lane] = nmv;
                kix[lane] = nvi;
                float4 r;
                r.x = nvx - c0; r.y = nvy - c1; r.z = nvz - c2; r.w = 0.f;
                rel4[lane] = r;
            }
            float t = sm[O_QPB + lane];
            t = fmaf(sm[O_QPW + lane*3+0], c0, t);
            t = fmaf(sm[O_QPW + lane*3+1], c1, t);
            t = fmaf(sm[O_QPW + lane*3+2], c2, t);
            qin_s[lane] = fmaxf(t, 0.f);
        }
        {   // prefetch next query's data
            int qn = q + step;
            int qc_ = (qn < m) ? qn : 0;
            nc0 = __ldg(&qcoord[qc_*3+0]);
            nc1 = __ldg(&qcoord[qc_*3+1]);
            nc2 = __ldg(&qcoord[qc_*3+2]);
            if (lane < K_) {
                const int idx = qc_ * K_ + lane;
                nvi = __ldg(&kidx[idx]);
                if (mode == 0)      nmv = ((const unsigned char*)kmask)[idx] ? 1.f : 0.f;
                else if (mode == 1) nmv = ((const int*)kmask)[idx] ? 1.f : 0.f;
                else                nmv = (((const float*)kmask)[idx] != 0.f) ? 1.f : 0.f;
                nvx = __ldg(&vcoord[nvi*3+0]);
                nvy = __ldg(&vcoord[nvi*3+1]);
                nvz = __ldg(&vcoord[nvi*3+2]);
            }
        }
        BAR64(bid);

        if (valid) {   // P2: q = (q_in @ wq^T + bq) * d^-0.5
            float acc = sm[O_BQ + lane];
            #pragma unroll
            for (int cp = 0; cp < 64; cp += 4) {
                float4 a = *(const float4*)&qin_s[cp];
                acc = fmaf(a.x, sm[O_WQT + (cp+0)*64 + lane], acc);
                acc = fmaf(a.y, sm[O_WQT + (cp+1)*64 + lane], acc);
                acc = fmaf(a.z, sm[O_WQT + (cp+2)*64 + lane], acc);
                acc = fmaf(a.w, sm[O_WQT + (cp+3)*64 + lane], acc);
            }
            qv_s[lane] = acc * 0.25f;
        }
        BAR64(bid);

        if (valid) {   // P3: u[h] = wk_h^T @ q_h ; gather -> fp16 kin (swizzled)
            #pragma unroll
            for (int h = 0; h < 4; h++) {
                float acc = 0.f;
                #pragma unroll
                for (int j4 = 0; j4 < 4; j4++) {
                    float4 qv = *(const float4*)&qv_s[h*16 + j4*4];
                    acc = fmaf(sm[O_WK + (h*16+j4*4+0)*64 + lane], qv.x, acc);
                    acc = fmaf(sm[O_WK + (h*16+j4*4+1)*64 + lane], qv.y, acc);
                    acc = fmaf(sm[O_WK + (h*16+j4*4+2)*64 + lane], qv.z, acc);
                    acc = fmaf(sm[O_WK + (h*16+j4*4+3)*64 + lane], qv.w, acc);
                }
                u_s[h*64 + lane] = acc;
            }
            #pragma unroll
            for (int kb = 0; kb < K_; kb += 16) {
                float fv[16];
                #pragma unroll
                for (int j = 0; j < 16; j++)
                    fv[j] = __ldg(&vf[kix[kb+j] * 64 + lane]);
                #pragma unroll
                for (int j = 0; j < 16; j++) {
                    const int k = kb + j;
                    float4 r = rel4[k];
                    float kp = kb_;
                    kp = fmaf(kw0, r.x, kp);
                    kp = fmaf(kw1, r.y, kp);
                    kp = fmaf(kw2, r.z, kp);
                    float val = fv[j] + fmaxf(kp, 0.f);
                    kinh[k*64 + ((lj ^ (k & 7)) << 3) + lp] = __float2half(val);
                }
            }
        }
        BAR64(bid);

        if (valid && lane < K_) {   // P4: scores — lane = key; 8x uint4 row reads
            const int k = lane, kx = k & 7;
            const char* krow = kinb + k * 128;
            float4 acc = make_float4(0.f, 0.f, 0.f, 0.f);
            #pragma unroll
            for (int ju = 0; ju < 8; ju++) {          // logical unit = channels ju*8..+7
                uint4 u4v = *(const uint4*)(krow + ((ju ^ kx) << 4));
                float2 f0 = h2f(u4v.x), f1 = h2f(u4v.y),
                       f2 = h2f(u4v.z), f3 = h2f(u4v.w);
                #pragma unroll
                for (int h = 0; h < 4; h++) {
                    float4 ua = *(const float4*)&u_s[h*64 + ju*8];
                    float4 ub = *(const float4*)&u_s[h*64 + ju*8 + 4];
                    float p;
                    p = fmaf(f0.x, ua.x, 0.f);
                    p = fmaf(f0.y, ua.y, p);
                    p = fmaf(f1.x, ua.z, p);
                    p = fmaf(f1.y, ua.w, p);
                    p = fmaf(f2.x, ub.x, p);
                    p = fmaf(f2.y, ub.y, p);
                    p = fmaf(f3.x, ub.z, p);
                    p = fmaf(f3.y, ub.w, p);
                    if (h == 0) acc.x += p;
                    else if (h == 1) acc.y += p;
                    else if (h == 2) acc.z += p;
                    else acc.w += p;
                }
            }
            if (msk[k] != 0.f) acc = make_float4(-1e9f, -1e9f, -1e9f, -1e9f);
            *(float4*)&sb[k*4] = acc;
        }
        BAR64(bid);

        if (valid) {   // P5: softmax
            const int h = lane >> 4, j = lane & 15;
            float v0 = sb[j*4+h], v1 = sb[(j+16)*4+h], v2 = sb[(j+32)*4+h];
            float mx = fmaxf(v0, fmaxf(v1, v2));
            #pragma unroll
            for (int off = 8; off; off >>= 1)
                mx = fmaxf(mx, __shfl_xor_sync(0xffffffffu, mx, off));
            float e0 = __expf(v0-mx), e1 = __expf(v1-mx), e2 = __expf(v2-mx);
            sb[j*4+h] = e0; sb[(j+16)*4+h] = e1; sb[(j+32)*4+h] = e2;
            float s = e0 + e1 + e2;
            #pragma unroll
            for (int off = 8; off; off >>= 1)
                s += __shfl_xor_sync(0xffffffffu, s, off);
            if (j == 0) inv[h] = 1.0f / s;
        }
        BAR64(bid);

        if (valid) {   // P6: ctx[h,c] = sum_k a[h,k] k_in[k,c]  (fp16 reads)
            float a0=0.f, a1=0.f, a2=0.f, a3=0.f;
            #pragma unroll 8
            for (int k = 0; k < K_; k++) {
                float4 e = *(const float4*)&sb[k*4];
                float kv = __half2float(kinh[k*64 + ((lj ^ (k & 7)) << 3) + lp]);
                a0 = fmaf(e.x, kv, a0); a1 = fmaf(e.y, kv, a1);
                a2 = fmaf(e.z, kv, a2); a3 = fmaf(e.w, kv, a3);
            }
            ctx[0*CTXSTR+lane] = a0*inv[0]; ctx[1*CTXSTR+lane] = a1*inv[1];
            ctx[2*CTXSTR+lane] = a2*inv[2]; ctx[3*CTXSTR+lane] = a3*inv[3];
        }
        BAR64(bid);

        if (valid) {   // P7: o = ctx @ wv^T + bv -> global
            const float4* cr4 = (const float4*)(ctx + (lane >> 4) * CTXSTR);
            float acc = sm[O_BV + lane];
            #pragma unroll 4
            for (int c4 = 0; c4 < 16; c4++) {
                float4 cv = cr4[c4];
                acc = fmaf(cv.x, sm[O_WVT + (c4*4+0)*64 + lane], acc);
                acc = fmaf(cv.y, sm[O_WVT + (c4*4+1)*64 + lane], acc);
                acc = fmaf(cv.z, sm[O_WVT + (c4*4+2)*64 + lane], acc);
                acc = fmaf(cv.w, sm[O_WVT + (c4*4+3)*64 + lane], acc);
            }
            g_obuf[q*64 + lane] = acc;
        }
    }
}

// ============================================================================
// ffn: out_proj + FFN + BN1 + output layer + BN2 + ReLU (unchanged)
// ============================================================================
__global__ __launch_bounds__(512, 1) void ffn_kernel(
    const float* __restrict__ opw, const float* __restrict__ opb,
    const float* __restrict__ w1,  const float* __restrict__ b1,
    const float* __restrict__ w2,  const float* __restrict__ b2,
    const float* __restrict__ ng,  const float* __restrict__ nb,
    const float* __restrict__ nm,  const float* __restrict__ nv,
    const float* __restrict__ ow,  const float* __restrict__ ob,
    const float* __restrict__ g2,  const float* __restrict__ b2n,
    const float* __restrict__ m2,  const float* __restrict__ v2,
    float* __restrict__ out, int m)
{
    extern __shared__ float sm[];
    const int tid = threadIdx.x;

    for (int i = tid; i < 4096; i += 512) {
        int c = i & 63, cp = i >> 6;
        sm[Q_WOT  + i] = opw[c*64 + cp];
        sm[Q_WOUT + i] = ow[c*64 + cp];
    }
    for (int i = tid; i < 16384; i += 512) {
        sm[Q_W1T + i] = w1[(i & 255)*64 + (i >> 8)];
        sm[Q_W2T + i] = w2[(i & 63)*256 + (i >> 6)];
    }
    if (tid < 64) {
        sm[Q_BO + tid] = opb[tid];
        sm[Q_B2 + tid] = b2[tid];
        sm[Q_OUTB + tid] = ob[tid];
        float s1 = ng[tid] * rsqrtf(nv[tid] + 1e-5f);
        sm[Q_BN1S + tid] = s1;
        sm[Q_BN1T + tid] = nb[tid] - nm[tid] * s1;
        float s2 = g2[tid] * rsqrtf(v2[tid] + 1e-5f);
        sm[Q_BN2S + tid] = s2;
        sm[Q_BN2T + tid] = b2n[tid] - m2[tid] * s2;
    }
    if (tid < 256) sm[Q_B1 + tid] = b1[tid];
    __syncthreads();

    const int g = tid >> 7;
    const int t = tid & 127;
    const int c = t & 63;
    const int half = t >> 6;
    const int bid = g + 1;
    const int jb = half * 4;
    float* G    = sm + Q_GRP + g * GRP_FL;
    float* o8   = G;
    float* att8 = G + 512;
    float* h8   = G + 1024;

    const float bo_ = sm[Q_BO + c];
    const float bb2 = sm[Q_B2 + c];
    const float s1 = sm[Q_BN1S + c], t1 = sm[Q_BN1T + c];
    const float obc = sm[Q_OUTB + c], s2 = sm[Q_BN2S + c], t2 = sm[Q_BN2T + c];
    const int f0 = half * 128 + c, f1 = f0 + 64;
    const float b1a = sm[Q_B1 + f0], b1b = sm[Q_B1 + f1];

    for (int qb = blockIdx.x * 32; qb < m; qb += gridDim.x * 32) {
        const int qg = qb + g * 8;

        float4 ov;
        ov.x = (qg+jb+0 < m) ? g_obuf[(qg+jb+0)*64 + c] : 0.f;
        ov.y = (qg+jb+1 < m) ? g_obuf[(qg+jb+1)*64 + c] : 0.f;
        ov.z = (qg+jb+2 < m) ? g_obuf[(qg+jb+2)*64 + c] : 0.f;
        ov.w = (qg+jb+3 < m) ? g_obuf[(qg+jb+3)*64 + c] : 0.f;
        *(float4*)&o8[c*8 + jb] = ov;
        BAR128(bid);

        float4 att = make_float4(bo_, bo_, bo_, bo_);
        #pragma unroll 8
        for (int cp = 0; cp < 64; cp++) {
            float w = sm[Q_WOT + cp*64 + c];
            float4 a = *(const float4*)&o8[cp*8 + jb];
            att.x = fmaf(a.x,w,att.x); att.y = fmaf(a.y,w,att.y);
            att.z = fmaf(a.z,w,att.z); att.w = fmaf(a.w,w,att.w);
        }
        *(float4*)&att8[c*8 + jb] = att;
        BAR128(bid);

        float h0[8], h1[8];
        #pragma unroll
        for (int j = 0; j < 8; j++) { h0[j] = b1a; h1[j] = b1b; }
        #pragma unroll 4
        for (int cp = 0; cp < 64; cp++) {
            float w0 = sm[Q_W1T + cp*256 + f0];
            float w1_ = sm[Q_W1T + cp*256 + f1];
            float4 alo = *(const float4*)&att8[cp*8];
            float4 ahi = *(const float4*)&att8[cp*8+4];
            h0[0]=fmaf(alo.x,w0,h0[0]); h0[1]=fmaf(alo.y,w0,h0[1]);
            h0[2]=fmaf(alo.z,w0,h0[2]); h0[3]=fmaf(alo.w,w0,h0[3]);
            h0[4]=fmaf(ahi.x,w0,h0[4]); h0[5]=fmaf(ahi.y,w0,h0[5]);
            h0[6]=fmaf(ahi.z,w0,h0[6]); h0[7]=fmaf(ahi.w,w0,h0[7]);
            h1[0]=fmaf(alo.x,w1_,h1[0]); h1[1]=fmaf(alo.y,w1_,h1[1]);
            h1[2]=fmaf(alo.z,w1_,h1[2]); h1[3]=fmaf(alo.w,w1_,h1[3]);
            h1[4]=fmaf(ahi.x,w1_,h1[4]); h1[5]=fmaf(ahi.y,w1_,h1[5]);
            h1[6]=fmaf(ahi.z,w1_,h1[6]); h1[7]=fmaf(ahi.w,w1_,h1[7]);
        }
        #pragma unroll
        for (int j = 0; j < 8; j++) { h0[j] = fmaxf(h0[j],0.f); h1[j] = fmaxf(h1[j],0.f); }
        *(float4*)&h8[f0*8]   = make_float4(h0[0],h0[1],h0[2],h0[3]);
        *(float4*)&h8[f0*8+4] = make_float4(h0[4],h0[5],h0[6],h0[7]);
        *(float4*)&h8[f1*8]   = make_float4(h1[0],h1[1],h1[2],h1[3]);
        *(float4*)&h8[f1*8+4] = make_float4(h1[4],h1[5],h1[6],h1[7]);
        BAR128(bid);

        float x[8];
        if (half == 0) {
            float4 alo = *(const float4*)&att8[c*8];
            float4 ahi = *(const float4*)&att8[c*8+4];
            x[0]=alo.x+bb2; x[1]=alo.y+bb2; x[2]=alo.z+bb2; x[3]=alo.w+bb2;
            x[4]=ahi.x+bb2; x[5]=ahi.y+bb2; x[6]=ahi.z+bb2; x[7]=ahi.w+bb2;
        } else {
            #pragma unroll
            for (int j = 0; j < 8; j++) x[j] = 0.f;
        }
        {
            const int fb = half * 128;
            #pragma unroll 4
            for (int fl = 0; fl < 128; fl++) {
                const int f = fb + fl;
                float w = sm[Q_W2T + f*64 + c];
                float4 hlo = *(const float4*)&h8[f*8];
                float4 hhi = *(const float4*)&h8[f*8+4];
                x[0]=fmaf(hlo.x,w,x[0]); x[1]=fmaf(hlo.y,w,x[1]);
                x[2]=fmaf(hlo.z,w,x[2]); x[3]=fmaf(hlo.w,w,x[3]);
                x[4]=fmaf(hhi.x,w,x[4]); x[5]=fmaf(hhi.y,w,x[5]);
                x[6]=fmaf(hhi.z,w,x[6]); x[7]=fmaf(hhi.w,w,x[7]);
            }
        }
        if (half == 1) {
            *(float4*)&o8[c*8]   = make_float4(x[0],x[1],x[2],x[3]);
            *(float4*)&o8[c*8+4] = make_float4(x[4],x[5],x[6],x[7]);
        }
        BAR128(bid);
        if (half == 0) {
            float4 plo = *(const float4*)&o8[c*8];
            float4 phi = *(const float4*)&o8[c*8+4];
            x[0]+=plo.x; x[1]+=plo.y; x[2]+=plo.z; x[3]+=plo.w;
            x[4]+=phi.x; x[5]+=phi.y; x[6]+=phi.z; x[7]+=phi.w;
            #pragma unroll
            for (int j = 0; j < 8; j++) x[j] = fmaf(x[j], s1, t1);
            *(float4*)&h8[c*8]   = make_float4(x[0],x[1],x[2],x[3]);
            *(float4*)&h8[c*8+4] = make_float4(x[4],x[5],x[6],x[7]);
        }
        BAR128(bid);

        float4 y = make_float4(0.f,0.f,0.f,0.f);
        #pragma unroll 8
        for (int cp = 0; cp < 64; cp++) {
            float w = sm[Q_WOUT + cp*64 + c];
            float4 xv = *(const float4*)&h8[cp*8 + jb];
            y.x = fmaf(xv.x,w,y.x); y.y = fmaf(xv.y,w,y.y);
            y.z = fmaf(xv.z,w,y.z); y.w = fmaf(xv.w,w,y.w);
        }
        y.x = fmaxf(fmaf(y.x+obc, s2, t2), 0.f);
        y.y = fmaxf(fmaf(y.y+obc, s2, t2), 0.f);
        y.z = fmaxf(fmaf(y.z+obc, s2, t2), 0.f);
        y.w = fmaxf(fmaf(y.w+obc, s2, t2), 0.f);
        if (qg+jb+0 < m) out[(qg+jb+0)*64 + c] = y.x;
        if (qg+jb+1 < m) out[(qg+jb+1)*64 + c] = y.y;
        if (qg+jb+2 < m) out[(qg+jb+2)*64 + c] = y.z;
        if (qg+jb+3 < m) out[(qg+jb+3)*64 + c] = y.w;
        BAR128(bid);
    }
}

extern "C" void kernel_launch(void* const* d_in, const int* in_sizes, int n_in,
                              void* d_out, int out_size)
{
    const float* vf  = (const float*)d_in[0];
    const float* vc  = (const float*)d_in[1];
    const float* qc  = (const float*)d_in[2];
    const int*   ki  = (const int*)d_in[3];
    const void*  km  = d_in[4];
    const float* qpw = (const float*)d_in[5];
    const float* qpb = (const float*)d_in[6];
    const float* kpw = (const float*)d_in[7];
    const float* kpb = (const float*)d_in[8];
    const float* ipw = (const float*)d_in[9];
    const float* ipb = (const float*)d_in[10];
    const float* opw = (const float*)d_in[11];
    const float* opb = (const float*)d_in[12];
    const float* w1  = (const float*)d_in[13];
    const float* b1  = (const float*)d_in[14];
    const float* w2  = (const float*)d_in[15];
    const float* b2  = (const float*)d_in[16];
    const float* ng  = (const float*)d_in[17];
    const float* nb  = (const float*)d_in[18];
    const float* nm  = (const float*)d_in[19];
    const float* nv  = (const float*)d_in[20];
    const float* ow  = (const float*)d_in[21];
    const float* ob  = (const float*)d_in[22];
    const float* g2  = (const float*)d_in[23];
    const float* b2n = (const float*)d_in[24];
    const float* m2  = (const float*)d_in[25];
    const float* v2  = (const float*)d_in[26];

    int m = in_sizes[2] / 3;
    if (m > MQ_MAX) m = MQ_MAX;

    cudaFuncSetAttribute(attn_kernel, cudaFuncAttributeMaxDynamicSharedMemorySize, SMEM1_BYTES);
    cudaFuncSetAttribute(ffn_kernel, cudaFuncAttributeMaxDynamicSharedMemorySize, SMEM2_BYTES);

    attn_kernel<<<148, THREADS1, SMEM1_BYTES>>>(vf, vc, qc, ki, km, qpw, qpb, kpw, kpb,
                                                ipw, ipb, m, (float*)d_out, (long long)out_size);
    ffn_kernel<<<148, 512, SMEM2_BYTES>>>(opw, opb, w1, b1, w2, b2, ng, nb, nm, nv,
                                          ow, ob, g2, b2n, m2, v2, (float*)d_out, m);
}